// round 9
// baseline (speedup 1.0000x reference)
#include <cuda_runtime.h>
#include <cstdint>

#define N_STEPS 1000

// Per-step key schedule, 2 uint4 records:
//  A = {k0, k1, k2, k2+1},  B = {k0+2, k1+3, k2+4, k0+5}
__device__ uint4 g_keysA[N_STEPS + 1];
__device__ uint4 g_keysB[N_STEPS + 1];

// pre-scale all erfinv coefficients by 0.1 * sqrt(2)
#define SC(c) (0.14142136f * (c))

// guaranteed single-instruction FFMA with [0,1] saturation (the clip)
__device__ __forceinline__ float fma_sat(float a, float b, float c) {
    float d;
    asm("fma.rn.sat.f32 %0, %1, %2, %3;" : "=f"(d) : "f"(a), "f"(b), "f"(c));
    return d;
}

// forced IMAD add (fma pipe): d = a*one + b, `one` is an opaque runtime 1
__device__ __forceinline__ uint32_t addm(uint32_t a, uint32_t b, uint32_t one) {
    uint32_t d;
    asm("mad.lo.u32 %0, %1, %2, %3;" : "=r"(d) : "r"(a), "r"(one), "r"(b));
    return d;
}

// ---------------- Threefry-2x32 ----------------
// round with the add forced onto the IMAD pipe; SHF+LOP3 stay on alu
__device__ __forceinline__ void rsm(uint32_t& x0, uint32_t& x1, int r, uint32_t one) {
    x0 = addm(x1, x0, one);                   // IMAD
    x1 = __funnelshift_l(x1, x1, r) ^ x0;     // SHF + LOP3 (alu)
}

// full 20-round block (c0 = 0 folded), returns o0 ^ o1 (partitionable random_bits)
__device__ __forceinline__ uint32_t tf_xor(uint4 ka, uint4 kb, uint32_t c1, uint32_t one) {
    uint32_t x1 = c1 + ka.y;                  // alu add
    uint32_t x0 = addm(x1, ka.x, one);        // round-1 add, x0-init folded (IMAD)
    x1 = __funnelshift_l(x1, x1, 13) ^ x0;
    rsm(x0, x1, 15, one); rsm(x0, x1, 26, one); rsm(x0, x1, 6, one);
    x0 = addm(x0, ka.y, one); x1 += ka.w;     // += k1 (IMAD) | += k2+1 (alu)
    rsm(x0, x1, 17, one); rsm(x0, x1, 29, one); rsm(x0, x1, 16, one); rsm(x0, x1, 24, one);
    x0 = addm(x0, ka.z, one); x1 += kb.x;     // += k2 | += k0+2
    rsm(x0, x1, 13, one); rsm(x0, x1, 15, one); rsm(x0, x1, 26, one); rsm(x0, x1, 6, one);
    x0 = addm(x0, ka.x, one); x1 += kb.y;     // += k0 | += k1+3
    rsm(x0, x1, 17, one); rsm(x0, x1, 29, one); rsm(x0, x1, 16, one); rsm(x0, x1, 24, one);
    x0 = addm(x0, ka.y, one); x1 += kb.z;     // += k1 | += k2+4
    rsm(x0, x1, 13, one); rsm(x0, x1, 15, one); rsm(x0, x1, 26, one); rsm(x0, x1, 6, one);
    return addm(x0, ka.z, one) ^ addm(x1, kb.w, one);   // (x0+k2) ^ (x1+k0+5)
}

// plain scalar threefry for key prep (perf-irrelevant)
__device__ __forceinline__ void rs_s(uint32_t& x0, uint32_t& x1, int r) {
    x0 += x1; x1 = __funnelshift_l(x1, x1, r) ^ x0;
}
__device__ void threefry2x32_full(uint32_t k0, uint32_t k1, uint32_t c0, uint32_t c1,
                                  uint32_t& o0, uint32_t& o1) {
    const uint32_t k2 = k0 ^ k1 ^ 0x1BD11BDAu;
    uint32_t x0 = c0 + k0, x1 = c1 + k1;
    rs_s(x0,x1,13); rs_s(x0,x1,15); rs_s(x0,x1,26); rs_s(x0,x1,6);
    x0 += k1; x1 += k2 + 1u;
    rs_s(x0,x1,17); rs_s(x0,x1,29); rs_s(x0,x1,16); rs_s(x0,x1,24);
    x0 += k2; x1 += k0 + 2u;
    rs_s(x0,x1,13); rs_s(x0,x1,15); rs_s(x0,x1,26); rs_s(x0,x1,6);
    x0 += k0; x1 += k1 + 3u;
    rs_s(x0,x1,17); rs_s(x0,x1,29); rs_s(x0,x1,16); rs_s(x0,x1,24);
    x0 += k1; x1 += k2 + 4u;
    rs_s(x0,x1,13); rs_s(x0,x1,15); rs_s(x0,x1,26); rs_s(x0,x1,6);
    o0 = x0 + k2; o1 = x1 + k0 + 5u;
}

__global__ void prep_keys_kernel() {
    int t = threadIdx.x;
    if (t > N_STEPS) return;
    uint32_t kk1 = (t < N_STEPS) ? 1u : 2u;
    uint32_t cc1 = (t < N_STEPS) ? (uint32_t)t : 999u;
    uint32_t o0, o1;
    threefry2x32_full(0u, kk1, 0u, cc1, o0, o1);
    uint32_t k0 = o0, k1 = o1, k2 = o0 ^ o1 ^ 0x1BD11BDAu;
    g_keysA[t] = make_uint4(k0, k1, k2, k2 + 1u);
    g_keysB[t] = make_uint4(k0 + 2u, k1 + 3u, k2 + 4u, k0 + 5u);
}

// rare tail branch of erfinv (w >= 5), coefficients pre-scaled; z = w - 2.5
__device__ __noinline__ float tailp(float z) {
    float zz = __fsqrt_rn(z + 2.5f) - 3.0f;
    float p = SC(-0.000200214257f);
    p = fmaf(p, zz, SC(0.000100950558f));
    p = fmaf(p, zz, SC(0.00134934322f));
    p = fmaf(p, zz, SC(-0.00367342844f));
    p = fmaf(p, zz, SC(0.00573950773f));
    p = fmaf(p, zz, SC(-0.0076224613f));
    p = fmaf(p, zz, SC(0.00943887047f));
    p = fmaf(p, zz, SC(1.00167406f));
    p = fmaf(p, zz, SC(2.83297682f));
    return p;
}

// central pipeline: bits -> {xx, z, p_central}   (no branch; tail patched by caller)
__device__ __forceinline__ void noise_central(uint32_t b, uint32_t mhi9,
                                              float& xx, float& z, float& p) {
    uint32_t fbits;   // (b >> 9) | 0x3f800000  ==  hi(b * 2^23) + 0x3f800000, one IMAD.HI
    asm("mad.hi.u32 %0, %1, %2, %3;"
        : "=r"(fbits) : "r"(b), "r"(mhi9), "r"(0x3f800000u));
    float f = __uint_as_float(fbits);                // [1, 2)
    float u = f - 1.0f;                              // [0, 1), exact
    // two-op form REQUIRED: -2.99999994f is not representable (rounds to -3.0f),
    // which would make xx hit exactly -1.0 for bits < 512 -> log(0) -> NaN.
    xx = fmaf(u, 2.0f, -0.99999994f);                // uniform in [nextafter(-1,0), 1)
    float t = fmaf(xx, -xx, 1.0f);                   // 1 - x^2 > 0
    z = fmaf(__log2f(t), -0.69314718f, -2.5f);       // w - 2.5
    // central Giles poly, top (z^8) coefficient dropped (R2-validated: rel_err 6.6e-6)
    p = SC(3.43273939e-07f);
    p = fmaf(p, z, SC(-3.5233877e-06f));
    p = fmaf(p, z, SC(-4.39150654e-06f));
    p = fmaf(p, z, SC(0.00021858087f));
    p = fmaf(p, z, SC(-0.00125372503f));
    p = fmaf(p, z, SC(-0.00417768164f));
    p = fmaf(p, z, SC(0.246640727f));
    p = fmaf(p, z, SC(1.50140941f));
}

__global__ void __launch_bounds__(256, 4)
diffusion_kernel(const float* __restrict__ x, float* __restrict__ out, int n,
                 uint32_t mhi9, uint32_t one) {
    __shared__ uint4 sA[N_STEPS + 1];
    __shared__ uint4 sB[N_STEPS + 1];
    for (int i = threadIdx.x; i <= N_STEPS; i += 256) {
        sA[i] = g_keysA[i];
        sB[i] = g_keysB[i];
    }
    __syncthreads();

    unsigned tid  = blockIdx.x * 256u + threadIdx.x;
    unsigned base = tid * 4u;
    if (base >= (unsigned)n) return;

    if (base + 4u <= (unsigned)n) {
        // ---- main path: 4 independent scalar chains per thread (ILP-4) ----
        float4 v4 = *reinterpret_cast<const float4*>(x + base);
        float v0 = v4.x, v1 = v4.y, v2 = v4.z, v3 = v4.w;
        const uint32_t c0 = base, c1 = base + 1u, c2 = base + 2u, c3 = base + 3u;
        const unsigned wmask = __activemask();

        // software-pipelined key fetch: ka/kb hold step t; prefetch t+1 at loop top
        uint4 ka = sA[0];
        uint4 kb = sB[0];

        #pragma unroll 1
        for (int t = 0; t < N_STEPS; ++t) {
            uint4 ka_n = sA[t + 1];       // prefetch: whole body to cover 29-cyc LDS
            uint4 kb_n = sB[t + 1];
            uint32_t b0 = tf_xor(ka, kb, c0, one);
            uint32_t b1 = tf_xor(ka, kb, c1, one);
            uint32_t b2 = tf_xor(ka, kb, c2, one);
            uint32_t b3 = tf_xor(ka, kb, c3, one);
            float xx0, xx1, xx2, xx3, z0, z1, z2, z3, p0, p1, p2, p3;
            noise_central(b0, mhi9, xx0, z0, p0);
            noise_central(b1, mhi9, xx1, z1, p1);
            noise_central(b2, mhi9, xx2, z2, p2);
            noise_central(b3, mhi9, xx3, z3, p3);
            // warp-uniform rare guard: no divergence on the common path
            float zm = fmaxf(fmaxf(z0, z1), fmaxf(z2, z3));
            if (__builtin_expect(__any_sync(wmask, zm >= 2.5f), 0)) {
                if (z0 >= 2.5f) p0 = tailp(z0);
                if (z1 >= 2.5f) p1 = tailp(z1);
                if (z2 >= 2.5f) p2 = tailp(z2);
                if (z3 >= 2.5f) p3 = tailp(z3);
            }
            v0 = fma_sat(p0, xx0, v0);    // clip(v + noise), single FFMA.SAT
            v1 = fma_sat(p1, xx1, v1);
            v2 = fma_sat(p2, xx2, v2);
            v3 = fma_sat(p3, xx3, v3);
            ka = ka_n;
            kb = kb_n;
        }
        {   // reverse diffusion: single denoise step; ka/kb already hold entry N_STEPS
            uint32_t b0 = tf_xor(ka, kb, c0, one);
            uint32_t b1 = tf_xor(ka, kb, c1, one);
            uint32_t b2 = tf_xor(ka, kb, c2, one);
            uint32_t b3 = tf_xor(ka, kb, c3, one);
            float xx0, xx1, xx2, xx3, z0, z1, z2, z3, p0, p1, p2, p3;
            noise_central(b0, mhi9, xx0, z0, p0);
            noise_central(b1, mhi9, xx1, z1, p1);
            noise_central(b2, mhi9, xx2, z2, p2);
            noise_central(b3, mhi9, xx3, z3, p3);
            if (z0 >= 2.5f) p0 = tailp(z0);
            if (z1 >= 2.5f) p1 = tailp(z1);
            if (z2 >= 2.5f) p2 = tailp(z2);
            if (z3 >= 2.5f) p3 = tailp(z3);
            v0 = fma_sat(-p0, xx0, v0);
            v1 = fma_sat(-p1, xx1, v1);
            v2 = fma_sat(-p2, xx2, v2);
            v3 = fma_sat(-p3, xx3, v3);
        }
        *reinterpret_cast<float4*>(out + base) = make_float4(v0, v1, v2, v3);
    } else {
        // scalar tail path (not hit for the 25165824-element shape)
        for (unsigned e = base; e < (unsigned)n; ++e) {
            float vv = x[e];
            for (int t = 0; t < N_STEPS; ++t) {
                float xx, z, p;
                noise_central(tf_xor(sA[t], sB[t], e, one), mhi9, xx, z, p);
                if (z >= 2.5f) p = tailp(z);
                vv = fma_sat(p, xx, vv);
            }
            float xx, z, p;
            noise_central(tf_xor(sA[N_STEPS], sB[N_STEPS], e, one), mhi9, xx, z, p);
            if (z >= 2.5f) p = tailp(z);
            out[e] = fma_sat(-p, xx, vv);
        }
    }
}

extern "C" void kernel_launch(void* const* d_in, const int* in_sizes, int n_in,
                              void* d_out, int out_size) {
    const float* x = (const float*)d_in[0];
    float* out     = (float*)d_out;
    int n = out_size;

    prep_keys_kernel<<<1, 1024>>>();

    unsigned threads = (unsigned)((n + 3) / 4);
    unsigned blocks  = (threads + 255u) / 256u;
    // mhi9 = 1<<23 (for IMAD.HI) and one = 1 (for IMAD adds) kept opaque to ptxas
    diffusion_kernel<<<blocks, 256>>>(x, out, n, 1u << 23, 1u);
}

// round 10
// speedup vs baseline: 1.0101x; 1.0101x over previous
#include <cuda_runtime.h>
#include <cstdint>

#define N_STEPS 1000
#define ELEMS 6

// Per-step key schedule, 2 uint4 records:
//  A = {k0, k1, k2, k2+1},  B = {k0+2, k1+3, k2+4, k0+5}
__device__ uint4 g_keysA[N_STEPS + 1];
__device__ uint4 g_keysB[N_STEPS + 1];

// pre-scale all erfinv coefficients by 0.1 * sqrt(2)
#define SC(c) (0.14142136f * (c))

// guaranteed single-instruction FFMA with [0,1] saturation (the clip)
__device__ __forceinline__ float fma_sat(float a, float b, float c) {
    float d;
    asm("fma.rn.sat.f32 %0, %1, %2, %3;" : "=f"(d) : "f"(a), "f"(b), "f"(c));
    return d;
}

// forced IMAD add (fma pipe): d = a*one + b, `one` is an opaque runtime 1
__device__ __forceinline__ uint32_t addm(uint32_t a, uint32_t b, uint32_t one) {
    uint32_t d;
    asm("mad.lo.u32 %0, %1, %2, %3;" : "=r"(d) : "r"(a), "r"(one), "r"(b));
    return d;
}

// ---------------- Threefry-2x32 ----------------
// round with the add forced onto the IMAD pipe; SHF+LOP3 stay on alu
__device__ __forceinline__ void rsm(uint32_t& x0, uint32_t& x1, int r, uint32_t one) {
    x0 = addm(x1, x0, one);                   // IMAD
    x1 = __funnelshift_l(x1, x1, r) ^ x0;     // SHF + LOP3 (alu)
}

// full 20-round block (c0 = 0 folded), returns o0 ^ o1 (partitionable random_bits)
__device__ __forceinline__ uint32_t tf_xor(uint4 ka, uint4 kb, uint32_t c1, uint32_t one) {
    uint32_t x1 = c1 + ka.y;                  // alu add
    uint32_t x0 = addm(x1, ka.x, one);        // round-1 add, x0-init folded (IMAD)
    x1 = __funnelshift_l(x1, x1, 13) ^ x0;
    rsm(x0, x1, 15, one); rsm(x0, x1, 26, one); rsm(x0, x1, 6, one);
    x0 = addm(x0, ka.y, one); x1 += ka.w;     // += k1 (IMAD) | += k2+1 (alu)
    rsm(x0, x1, 17, one); rsm(x0, x1, 29, one); rsm(x0, x1, 16, one); rsm(x0, x1, 24, one);
    x0 = addm(x0, ka.z, one); x1 += kb.x;     // += k2 | += k0+2
    rsm(x0, x1, 13, one); rsm(x0, x1, 15, one); rsm(x0, x1, 26, one); rsm(x0, x1, 6, one);
    x0 = addm(x0, ka.x, one); x1 += kb.y;     // += k0 | += k1+3
    rsm(x0, x1, 17, one); rsm(x0, x1, 29, one); rsm(x0, x1, 16, one); rsm(x0, x1, 24, one);
    x0 = addm(x0, ka.y, one); x1 += kb.z;     // += k1 | += k2+4
    rsm(x0, x1, 13, one); rsm(x0, x1, 15, one); rsm(x0, x1, 26, one); rsm(x0, x1, 6, one);
    return addm(x0, ka.z, one) ^ addm(x1, kb.w, one);   // (x0+k2) ^ (x1+k0+5)
}

// plain scalar threefry for key prep (perf-irrelevant)
__device__ __forceinline__ void rs_s(uint32_t& x0, uint32_t& x1, int r) {
    x0 += x1; x1 = __funnelshift_l(x1, x1, r) ^ x0;
}
__device__ void threefry2x32_full(uint32_t k0, uint32_t k1, uint32_t c0, uint32_t c1,
                                  uint32_t& o0, uint32_t& o1) {
    const uint32_t k2 = k0 ^ k1 ^ 0x1BD11BDAu;
    uint32_t x0 = c0 + k0, x1 = c1 + k1;
    rs_s(x0,x1,13); rs_s(x0,x1,15); rs_s(x0,x1,26); rs_s(x0,x1,6);
    x0 += k1; x1 += k2 + 1u;
    rs_s(x0,x1,17); rs_s(x0,x1,29); rs_s(x0,x1,16); rs_s(x0,x1,24);
    x0 += k2; x1 += k0 + 2u;
    rs_s(x0,x1,13); rs_s(x0,x1,15); rs_s(x0,x1,26); rs_s(x0,x1,6);
    x0 += k0; x1 += k1 + 3u;
    rs_s(x0,x1,17); rs_s(x0,x1,29); rs_s(x0,x1,16); rs_s(x0,x1,24);
    x0 += k1; x1 += k2 + 4u;
    rs_s(x0,x1,13); rs_s(x0,x1,15); rs_s(x0,x1,26); rs_s(x0,x1,6);
    o0 = x0 + k2; o1 = x1 + k0 + 5u;
}

__global__ void prep_keys_kernel() {
    int t = threadIdx.x;
    if (t > N_STEPS) return;
    uint32_t kk1 = (t < N_STEPS) ? 1u : 2u;
    uint32_t cc1 = (t < N_STEPS) ? (uint32_t)t : 999u;
    uint32_t o0, o1;
    threefry2x32_full(0u, kk1, 0u, cc1, o0, o1);
    uint32_t k0 = o0, k1 = o1, k2 = o0 ^ o1 ^ 0x1BD11BDAu;
    g_keysA[t] = make_uint4(k0, k1, k2, k2 + 1u);
    g_keysB[t] = make_uint4(k0 + 2u, k1 + 3u, k2 + 4u, k0 + 5u);
}

// rare tail branch of erfinv (w >= 5), coefficients pre-scaled; z = w - 2.5
__device__ __noinline__ float tailp(float z) {
    float zz = __fsqrt_rn(z + 2.5f) - 3.0f;
    float p = SC(-0.000200214257f);
    p = fmaf(p, zz, SC(0.000100950558f));
    p = fmaf(p, zz, SC(0.00134934322f));
    p = fmaf(p, zz, SC(-0.00367342844f));
    p = fmaf(p, zz, SC(0.00573950773f));
    p = fmaf(p, zz, SC(-0.0076224613f));
    p = fmaf(p, zz, SC(0.00943887047f));
    p = fmaf(p, zz, SC(1.00167406f));
    p = fmaf(p, zz, SC(2.83297682f));
    return p;
}

// central pipeline: bits -> {xx, z, p_central}   (no branch; tail patched by caller)
__device__ __forceinline__ void noise_central(uint32_t b, uint32_t mhi9,
                                              float& xx, float& z, float& p) {
    uint32_t fbits;   // (b >> 9) | 0x3f800000  ==  hi(b * 2^23) + 0x3f800000, one IMAD.HI
    asm("mad.hi.u32 %0, %1, %2, %3;"
        : "=r"(fbits) : "r"(b), "r"(mhi9), "r"(0x3f800000u));
    float f = __uint_as_float(fbits);                // [1, 2)
    float u = f - 1.0f;                              // [0, 1), exact
    // two-op form REQUIRED: -2.99999994f is not representable (rounds to -3.0f),
    // which would make xx hit exactly -1.0 for bits < 512 -> log(0) -> NaN.
    xx = fmaf(u, 2.0f, -0.99999994f);                // uniform in [nextafter(-1,0), 1)
    float t = fmaf(xx, -xx, 1.0f);                   // 1 - x^2 > 0
    z = fmaf(__log2f(t), -0.69314718f, -2.5f);       // w - 2.5
    // central Giles poly, top (z^8) coefficient dropped (R2-validated: rel_err 6.6e-6)
    p = SC(3.43273939e-07f);
    p = fmaf(p, z, SC(-3.5233877e-06f));
    p = fmaf(p, z, SC(-4.39150654e-06f));
    p = fmaf(p, z, SC(0.00021858087f));
    p = fmaf(p, z, SC(-0.00125372503f));
    p = fmaf(p, z, SC(-0.00417768164f));
    p = fmaf(p, z, SC(0.246640727f));
    p = fmaf(p, z, SC(1.50140941f));
}

// 768 threads/SM (3 blocks) -> 85-reg budget: room for 6 fully-parallel chains
__global__ void __launch_bounds__(256, 3)
diffusion_kernel(const float* __restrict__ x, float* __restrict__ out, int n,
                 uint32_t mhi9, uint32_t one) {
    __shared__ uint4 sA[N_STEPS + 1];
    __shared__ uint4 sB[N_STEPS + 1];
    for (int i = threadIdx.x; i <= N_STEPS; i += 256) {
        sA[i] = g_keysA[i];
        sB[i] = g_keysB[i];
    }
    __syncthreads();

    unsigned tid  = blockIdx.x * 256u + threadIdx.x;
    unsigned base = tid * (unsigned)ELEMS;
    if (base >= (unsigned)n) return;

    if (base + (unsigned)ELEMS <= (unsigned)n) {
        // ---- main path: 6 independent scalar chains per thread (ILP-6) ----
        float v[ELEMS];
        {   // 6 floats = 3x float2 (8-byte aligned)
            const float2* xp = reinterpret_cast<const float2*>(x + base);
            float2 a = xp[0], b = xp[1], c = xp[2];
            v[0] = a.x; v[1] = a.y; v[2] = b.x; v[3] = b.y; v[4] = c.x; v[5] = c.y;
        }
        uint32_t cc[ELEMS];
        #pragma unroll
        for (int j = 0; j < ELEMS; ++j) cc[j] = base + (uint32_t)j;
        const unsigned wmask = __activemask();

        #pragma unroll 1
        for (int t = 0; t < N_STEPS; ++t) {
            uint4 ka = sA[t];
            uint4 kb = sB[t];
            uint32_t b[ELEMS];
            #pragma unroll
            for (int j = 0; j < ELEMS; ++j)
                b[j] = tf_xor(ka, kb, cc[j], one);
            float xx[ELEMS], z[ELEMS], p[ELEMS];
            #pragma unroll
            for (int j = 0; j < ELEMS; ++j)
                noise_central(b[j], mhi9, xx[j], z[j], p[j]);
            // warp-uniform rare guard: no divergence on the common path
            float zm = fmaxf(fmaxf(fmaxf(z[0], z[1]), fmaxf(z[2], z[3])),
                             fmaxf(z[4], z[5]));
            if (__builtin_expect(__any_sync(wmask, zm >= 2.5f), 0)) {
                #pragma unroll
                for (int j = 0; j < ELEMS; ++j)
                    if (z[j] >= 2.5f) p[j] = tailp(z[j]);
            }
            #pragma unroll
            for (int j = 0; j < ELEMS; ++j)
                v[j] = fma_sat(p[j], xx[j], v[j]);   // clip(v + noise)
        }
        {   // reverse diffusion: single denoise step (subtract)
            uint4 ka = sA[N_STEPS];
            uint4 kb = sB[N_STEPS];
            uint32_t b[ELEMS];
            #pragma unroll
            for (int j = 0; j < ELEMS; ++j)
                b[j] = tf_xor(ka, kb, cc[j], one);
            float xx[ELEMS], z[ELEMS], p[ELEMS];
            #pragma unroll
            for (int j = 0; j < ELEMS; ++j) {
                noise_central(b[j], mhi9, xx[j], z[j], p[j]);
                if (z[j] >= 2.5f) p[j] = tailp(z[j]);
                v[j] = fma_sat(-p[j], xx[j], v[j]);
            }
        }
        {
            float2* op = reinterpret_cast<float2*>(out + base);
            op[0] = make_float2(v[0], v[1]);
            op[1] = make_float2(v[2], v[3]);
            op[2] = make_float2(v[4], v[5]);
        }
    } else {
        // scalar tail path (not hit when n % 6 == 0, e.g. the 25165824-element shape)
        for (unsigned e = base; e < (unsigned)n; ++e) {
            float vv = x[e];
            for (int t = 0; t < N_STEPS; ++t) {
                float xx, z, p;
                noise_central(tf_xor(sA[t], sB[t], e, one), mhi9, xx, z, p);
                if (z >= 2.5f) p = tailp(z);
                vv = fma_sat(p, xx, vv);
            }
            float xx, z, p;
            noise_central(tf_xor(sA[N_STEPS], sB[N_STEPS], e, one), mhi9, xx, z, p);
            if (z >= 2.5f) p = tailp(z);
            out[e] = fma_sat(-p, xx, vv);
        }
    }
}

extern "C" void kernel_launch(void* const* d_in, const int* in_sizes, int n_in,
                              void* d_out, int out_size) {
    const float* x = (const float*)d_in[0];
    float* out     = (float*)d_out;
    int n = out_size;

    prep_keys_kernel<<<1, 1024>>>();

    unsigned threads = (unsigned)((n + ELEMS - 1) / ELEMS);
    unsigned blocks  = (threads + 255u) / 256u;
    // mhi9 = 1<<23 (for IMAD.HI) and one = 1 (for IMAD adds) kept opaque to ptxas
    diffusion_kernel<<<blocks, 256>>>(x, out, n, 1u << 23, 1u);
}